// round 17
// baseline (speedup 1.0000x reference)
#include <cuda_runtime.h>

// Problem constants
#define T_STEPS 512
#define NBATCH  512
#define IN_DIM  64
#define H       100

// Exact (unpadded) concat lengths:
// L1 input [x(64) | h1(100)]   -> 164 floats: 8 chunks of 10 u64 + 4 tail floats (lanes 0-3)
// L2 input [h1(100) | h2(100)] -> 200 floats: 8 chunks of 12 u64 + 8 tail floats (all lanes)
#define L1_LEN  164
#define L2_LEN  200

#define ROWS     4      // batch rows per CTA
#define NCTA     128    // 128 * 4 = 512 rows
#define NTHREADS 256    // 8 warps: wid 0-3 L1, wid 4-7 L2

typedef unsigned long long ull;

__device__ float g_W1T[H * L1_LEN];   // [col][k], transposed + concatenated, NO padding
__device__ float g_W2T[H * L2_LEN];

__global__ void prep_kernel(const float* __restrict__ W1x, const float* __restrict__ W1h,
                            const float* __restrict__ W2x, const float* __restrict__ W2h) {
    int idx = blockIdx.x * blockDim.x + threadIdx.x;
    const int n1 = H * L1_LEN;
    if (idx < n1) {
        int j = idx / L1_LEN, k = idx % L1_LEN;
        g_W1T[idx] = (k < IN_DIM) ? W1x[k * H + j] : W1h[(k - IN_DIM) * H + j];
    } else {
        int i2 = idx - n1;
        if (i2 < H * L2_LEN) {
            int j = i2 / L2_LEN, k = i2 % L2_LEN;
            g_W2T[i2] = (k < H) ? W2x[k * H + j] : W2h[(k - H) * H + j];
        }
    }
}

// Accurate fast tanh: 1 - 2/(exp(2x)+1).  __expf = MUFU.EX2 path, rel err ~1e-6.
__device__ __forceinline__ float fast_tanh(float x) {
    float e = __expf(2.0f * x);
    return 1.0f - __fdividef(2.0f, e + 1.0f);
}

// Packed fp32 FMA (sm_103a FFMA2): acc = a*b + acc, two k-lanes at once.
__device__ __forceinline__ void ffma2(ull& acc, ull a, ull b) {
    asm("fma.rn.f32x2 %0, %1, %2, %0;" : "+l"(acc) : "l"(a), "l"(b));
}

__device__ __forceinline__ float hadd2(ull a) {
    float lo, hi;
    asm("mov.b64 {%0, %1}, %2;" : "=f"(lo), "=f"(hi) : "l"(a));
    return lo + hi;
}

// Reduce-scatter CPT partials (per row, 2 rows interleaved for ILP) over the
// 8 k-split lanes of a group. Lane s ends with D[r2] = full sum of value s
// (s >= CPT lanes get dummies).  Exactly R9's reduce7 generalized.
template<int CPT>
__device__ __forceinline__ void reduceN(const float (&A)[2][CPT], int s, float (&D)[2]) {
    const bool h4 = (s & 4) != 0, h2 = (s & 2) != 0, h1 = (s & 1) != 0;
    float B[2][4];
    #pragma unroll
    for (int r2 = 0; r2 < 2; ++r2) {
        #pragma unroll
        for (int k = 0; k < 4; ++k) {
            float other = (k + 4 < CPT) ? A[r2][k + 4] : 0.0f;
            float self  = (k < CPT) ? A[r2][k] : 0.0f;
            float send = h4 ? self : other;
            float keep = h4 ? other : self;
            B[r2][k] = keep + __shfl_xor_sync(0xffffffffu, send, 4);
        }
    }
    float Cv[2][2];
    #pragma unroll
    for (int r2 = 0; r2 < 2; ++r2) {
        #pragma unroll
        for (int k = 0; k < 2; ++k) {
            float send = h2 ? B[r2][k] : B[r2][k + 2];
            float keep = h2 ? B[r2][k + 2] : B[r2][k];
            Cv[r2][k] = keep + __shfl_xor_sync(0xffffffffu, send, 2);
        }
    }
    #pragma unroll
    for (int r2 = 0; r2 < 2; ++r2) {
        float send = h1 ? Cv[r2][0] : Cv[r2][1];
        float keep = h1 ? Cv[r2][1] : Cv[r2][0];
        D[r2] = keep + __shfl_xor_sync(0xffffffffu, send, 1);
    }
}

// One warp's full time-loop. Exactly (T_STEPS+1) __syncthreads on every path.
template<int CPT, int LAYER>
__device__ __forceinline__ void run_loop(
    float* __restrict__ s1, float* __restrict__ s2,     // flattened [2][ROWS][LEN]
    const float4* __restrict__ xg4,
    const float* __restrict__ bias,
    float* __restrict__ out, int b0,
    int colBase, int lane, bool isPre, int pre_r, int pre_d)
{
    constexpr int NP     = (LAYER == 1) ? 10 : 12;      // u64 per k-chunk
    constexpr int ROWLEN = (LAYER == 1) ? L1_LEN : L2_LEN;
    constexpr int TAILK  = (LAYER == 1) ? 160 : 192;
    const int g = lane >> 3, s = lane & 7;
    const bool tailAct = (LAYER == 1) ? (s < 4) : true;
    const float* __restrict__ W = (LAYER == 1) ? g_W1T : g_W2T;

    // Weights: CPT columns x (NP u64 + 1 tail float).  Worst (CPT7,L2): 175 regs.
    ull   w[CPT][NP];
    float wt[CPT];
    #pragma unroll
    for (int c = 0; c < CPT; ++c) {
        const int col = colBase + g * CPT + c;
        const ull* p = (const ull*)(W + col * ROWLEN) + s * NP;
        #pragma unroll
        for (int i = 0; i < NP; ++i) w[c][i] = p[i];
        wt[c] = tailAct ? W[col * ROWLEN + TAILK + s] : 0.0f;
    }

    // Lane s owns column (colBase + g*CPT + s) for rows rb, rb+1.
    const bool ostore = (s < CPT);
    const int  ocol   = colBase + g * CPT + (ostore ? s : 0);
    const float biasv = bias[ocol];

    for (int p = 0; p <= T_STEPS; ++p) {
        const int pb = p & 1;

        float4 xpre;
        const bool doPre = isPre && (p + 1 < T_STEPS);
        if (doPre)
            xpre = xg4[(b0 + pre_r) * (T_STEPS * (IN_DIM / 4)) + (p + 1) * (IN_DIM / 4) + pre_d];

        const bool active = (LAYER == 1) ? (p < T_STEPS) : (p >= 1);
        if (active) {
            #pragma unroll
            for (int rb = 0; rb < ROWS; rb += 2) {
                float A[2][CPT];
                #pragma unroll
                for (int r2 = 0; r2 < 2; ++r2) {
                    const float* row = (LAYER == 1)
                        ? (s1 + (pb * ROWS + rb + r2) * L1_LEN)
                        : (s2 + (pb * ROWS + rb + r2) * L2_LEN);
                    const ull* vin = (const ull*)row + s * NP;
                    const float vt = tailAct ? row[TAILK + s] : 0.0f;
                    ull acc[CPT];
                    #pragma unroll
                    for (int c = 0; c < CPT; ++c) acc[c] = 0ull;
                    #pragma unroll
                    for (int i = 0; i < NP; ++i) {
                        ull vv = vin[i];
                        #pragma unroll
                        for (int c = 0; c < CPT; ++c) ffma2(acc[c], w[c][i], vv);
                    }
                    #pragma unroll
                    for (int c = 0; c < CPT; ++c)
                        A[r2][c] = fmaf(wt[c], vt, hadd2(acc[c]));
                }

                float D[2];
                reduceN<CPT>(A, s, D);
                const int nb = pb ^ 1;
                #pragma unroll
                for (int r2 = 0; r2 < 2; ++r2) {
                    float h = fast_tanh(D[r2] + biasv);
                    if (ostore) {
                        const int r = rb + r2;
                        if (LAYER == 1) {
                            s1[(nb * ROWS + r) * L1_LEN + IN_DIM + ocol] = h;  // next L1 h1(t-1)
                            s2[(nb * ROWS + r) * L2_LEN + ocol]          = h;  // next L2 h1(t-1)
                            if (p == T_STEPS - 1)
                                out[NBATCH + (b0 + r) * H + ocol] = h;         // h1_T
                        } else {
                            s2[(nb * ROWS + r) * L2_LEN + H + ocol] = h;       // next L2 h2(t-1)
                            if (p == T_STEPS)
                                out[NBATCH + NBATCH * H + (b0 + r) * H + ocol] = h;  // h2_T
                        }
                    }
                }
            }
        }

        if (doPre)
            ((float4*)(s1 + ((pb ^ 1) * ROWS + pre_r) * L1_LEN))[pre_d] = xpre;

        __syncthreads();
    }
}

__global__ void __launch_bounds__(NTHREADS, 1)
rnn_kernel(const float* __restrict__ x,
           const float* __restrict__ b1, const float* __restrict__ b2,
           const float* __restrict__ Wo, const float* __restrict__ bo,
           float* __restrict__ out) {
    __shared__ __align__(16) float s_in1[2][ROWS][L1_LEN];
    __shared__ __align__(16) float s_in2[2][ROWS][L2_LEN];
    float* s1 = &s_in1[0][0][0];
    float* s2 = &s_in2[0][0][0];

    const int t    = threadIdx.x;
    const int wid  = t >> 5;
    const int lane = t & 31;
    const int b0   = blockIdx.x * ROWS;
    const float4* __restrict__ xg4 = (const float4*)x;

    for (int i = t; i < 2 * ROWS * L1_LEN; i += NTHREADS) s1[i] = 0.0f;
    for (int i = t; i < 2 * ROWS * L2_LEN; i += NTHREADS) s2[i] = 0.0f;
    __syncthreads();

    // Stage x(0) into buffer 0 (threads 0-63; one-time).
    if (t < 64) {
        int pr = (t >> 4) & 3, pd = t & 15;
        ((float4*)(s1 + pr * L1_LEN))[pd] =
            xg4[(b0 + pr) * (T_STEPS * (IN_DIM / 4)) + pd];
    }
    __syncthreads();

    // Steady-state x prefetch on wid 6,7 (lightest SMSPs: both CPT6).
    const bool isPre = (t >= 192);
    const int  pre_r = (t >> 4) & 3, pre_d = t & 15;

    // Warp dispatch. SMSP = wid & 3.
    //   L1: wid0 CPT7 cols 0-27 | wid1 CPT6 28-51 | wid2 CPT6 52-75 | wid3 CPT6 76-99
    //   L2: wid5 CPT7 cols 0-27 | wid4 CPT6 28-51 | wid6 CPT6 52-75 | wid7 CPT6 76-99
    // Per-SMSP FFMA2: 568 / 576 / 528 / 528 (vs R9's 672 everywhere).
    if      (wid == 0) run_loop<7, 1>(s1, s2, xg4, b1, out, b0, 0,  lane, false, 0, 0);
    else if (wid == 1) run_loop<6, 1>(s1, s2, xg4, b1, out, b0, 28, lane, false, 0, 0);
    else if (wid == 2) run_loop<6, 1>(s1, s2, xg4, b1, out, b0, 52, lane, false, 0, 0);
    else if (wid == 3) run_loop<6, 1>(s1, s2, xg4, b1, out, b0, 76, lane, false, 0, 0);
    else if (wid == 5) run_loop<7, 2>(s1, s2, xg4, b2, out, b0, 0,  lane, false, 0, 0);
    else if (wid == 4) run_loop<6, 2>(s1, s2, xg4, b2, out, b0, 28, lane, false, 0, 0);
    else if (wid == 6) run_loop<6, 2>(s1, s2, xg4, b2, out, b0, 52, lane, isPre, pre_r, pre_d);
    else               run_loop<6, 2>(s1, s2, xg4, b2, out, b0, 76, lane, isPre, pre_r, pre_d);

    // out = h2_T @ Wo + bo.  h2(T-1) written at phase 512 (pb=0) into buffer 1,
    // ordered by the loops' final __syncthreads.
    if (t < ROWS) {
        float acc = bo[0];
        #pragma unroll 4
        for (int k = 0; k < H; ++k)
            acc = fmaf(s2[(1 * ROWS + t) * L2_LEN + H + k], Wo[k], acc);
        out[b0 + t] = acc;
    }
}

extern "C" void kernel_launch(void* const* d_in, const int* in_sizes, int n_in,
                              void* d_out, int out_size) {
    const float* x   = (const float*)d_in[0];
    const float* W1x = (const float*)d_in[1];
    const float* W1h = (const float*)d_in[2];
    const float* b1  = (const float*)d_in[3];
    const float* W2x = (const float*)d_in[4];
    const float* W2h = (const float*)d_in[5];
    const float* b2  = (const float*)d_in[6];
    const float* Wo  = (const float*)d_in[7];
    const float* bo  = (const float*)d_in[8];
    float* out = (float*)d_out;

    // Build transposed weight images (36400 elements, no padding).
    prep_kernel<<<143, 256>>>(W1x, W1h, W2x, W2h);

    // Persistent batch-partitioned RNN: 128 CTAs x 4 rows, no inter-CTA sync.
    rnn_kernel<<<NCTA, NTHREADS>>>(x, b1, b2, Wo, bo, out);
}